// round 8
// baseline (speedup 1.0000x reference)
#include <cuda_runtime.h>
#include <cstdint>

#define B_SZ 512
#define IN_F 512
#define OUT_F 100
#define KD 5
#define OC 500              // OUT_F * KD
#define LOG2E 1.4426950408889634f
#define NT 32               // number of batch tiles
#define TS 16               // tile size (NT*TS = B_SZ)
#define NP 528              // NT*(NT+1)/2 unordered tile pairs
#define MD_BLOCKS 264       // 2 pairs per block -> single wave at occ 2

// Scratch for M = (x @ T) * log2(e), laid out [b][o*5+k], 512x500 floats = 1MB
__device__ float g_M[B_SZ * OC];

__device__ __forceinline__ float ex2(float x) {
    float r;
    asm("ex2.approx.f32 %0, %1;" : "=f"(r) : "f"(x));
    return r;
}

// cumulative pair count before tile-row a (upper triangle incl. diagonal)
__device__ __forceinline__ int cum(int a) { return a * NT - (a * (a - 1)) / 2; }

// ---------------------------------------------------------------------------
// Kernel 1: M[b][oc] = sum_i x[b][i] * T[i][oc], scaled by log2e.
// 512 threads = 64 oc-pair-lanes x 8 K-slices; 3-step smem tree reduction.
// Grid (64, 4). Also zeroes `out` (blockIdx.y == 0 slice).
// ---------------------------------------------------------------------------
__global__ void __launch_bounds__(512) gemm_kernel(const float* __restrict__ x,
                                                   const float* __restrict__ T,
                                                   float* __restrict__ out) {
    __shared__ __align__(16) float xs[IN_F * 8];          // [i][bb], 16KB
    __shared__ __align__(16) float red[4 * 8 * 128];      // 4 slices, 16KB

    const int t = threadIdx.x;
    const int lane = t & 63;
    const int kh = t >> 6;
    const int b0 = blockIdx.x * 8;
    const int oc0 = blockIdx.y * 128;
    const int oc = oc0 + lane * 2;
    const bool ocv = (oc < OC);

    if (blockIdx.y == 0) {
        for (int idx = blockIdx.x * 512 + t; idx < B_SZ * OUT_F; idx += 64 * 512)
            out[idx] = 0.0f;
    }

    for (int idx = t; idx < IN_F * 8; idx += 512) {
        int bb = idx >> 9;
        int i = idx & (IN_F - 1);
        xs[i * 8 + bb] = x[(b0 + bb) * IN_F + i];
    }
    __syncthreads();

    float accx[8] = {0.f, 0.f, 0.f, 0.f, 0.f, 0.f, 0.f, 0.f};
    float accy[8] = {0.f, 0.f, 0.f, 0.f, 0.f, 0.f, 0.f, 0.f};

    if (ocv) {
        const float* tp = T + (size_t)(kh * 64) * OC + oc;
        const float* xp = xs + kh * 64 * 8;
#pragma unroll 8
        for (int i = 0; i < 64; i++) {
            float2 tv = *reinterpret_cast<const float2*>(tp + i * OC);
            float4 xa = *reinterpret_cast<const float4*>(xp + i * 8);
            float4 xb = *reinterpret_cast<const float4*>(xp + i * 8 + 4);
            accx[0] += xa.x * tv.x; accy[0] += xa.x * tv.y;
            accx[1] += xa.y * tv.x; accy[1] += xa.y * tv.y;
            accx[2] += xa.z * tv.x; accy[2] += xa.z * tv.y;
            accx[3] += xa.w * tv.x; accy[3] += xa.w * tv.y;
            accx[4] += xb.x * tv.x; accy[4] += xb.x * tv.y;
            accx[5] += xb.y * tv.x; accy[5] += xb.y * tv.y;
            accx[6] += xb.z * tv.x; accy[6] += xb.z * tv.y;
            accx[7] += xb.w * tv.x; accy[7] += xb.w * tv.y;
        }
    }

    // tree reduction of 8 kh-slices
    if (kh >= 4) {
        float* rp = red + (kh - 4) * 1024 + lane * 2;
#pragma unroll
        for (int bb = 0; bb < 8; bb++) { rp[bb * 128] = accx[bb]; rp[bb * 128 + 1] = accy[bb]; }
    }
    __syncthreads();
    if (kh < 4) {
        const float* rp = red + kh * 1024 + lane * 2;
#pragma unroll
        for (int bb = 0; bb < 8; bb++) { accx[bb] += rp[bb * 128]; accy[bb] += rp[bb * 128 + 1]; }
    }
    __syncthreads();
    if (kh == 2 || kh == 3) {
        float* rp = red + (kh - 2) * 1024 + lane * 2;
#pragma unroll
        for (int bb = 0; bb < 8; bb++) { rp[bb * 128] = accx[bb]; rp[bb * 128 + 1] = accy[bb]; }
    }
    __syncthreads();
    if (kh < 2) {
        const float* rp = red + kh * 1024 + lane * 2;
#pragma unroll
        for (int bb = 0; bb < 8; bb++) { accx[bb] += rp[bb * 128]; accy[bb] += rp[bb * 128 + 1]; }
    }
    __syncthreads();
    if (kh == 1) {
        float* rp = red + lane * 2;
#pragma unroll
        for (int bb = 0; bb < 8; bb++) { rp[bb * 128] = accx[bb]; rp[bb * 128 + 1] = accy[bb]; }
    }
    __syncthreads();
    if (kh == 0 && ocv) {
#pragma unroll
        for (int bb = 0; bb < 8; bb++) {
            float2 o2;
            o2.x = (accx[bb] + red[bb * 128 + lane * 2 + 0]) * LOG2E;
            o2.y = (accy[bb] + red[bb * 128 + lane * 2 + 1]) * LOG2E;
            *reinterpret_cast<float2*>(&g_M[(size_t)(b0 + bb) * OC + oc]) = o2;
        }
    }
}

// ---------------------------------------------------------------------------
// Kernel 2: two tile-pairs per 800-thread block (264 blocks = single wave at
// occ 2 -> 50 warps/SM). Half h = t/400 owns pair p = 2*blockIdx.x + h with
// its own smem tile. Within a half: o = tl>>2, jl = tl&3, r=4 j-rows per
// thread (JR=4 amortizes d-loads/shfl/loop over 4 evals). 400 % 4 == 0 so
// the 4-lane shfl groups never straddle halves. Closed-form pair decode.
// ---------------------------------------------------------------------------
__global__ void __launch_bounds__(800, 2) md_kernel(float* __restrict__ out) {
    __shared__ __align__(16) float ms[2 * TS * OC];  // 64KB, one tile per half

    const int t = threadIdx.x;
    const int h = (t >= 400) ? 1 : 0;
    const int tl = t - h * 400;
    const int o = tl >> 2;       // 0..99
    const int jl = tl & 3;       // 0..3

    // decode p -> (ta, tb) in closed form (disc is a perfect square exactly
    // at tile boundaries -> fp32-exact there; +/-1 fixup covers rounding)
    const int p = 2 * blockIdx.x + h;            // 0..527
    int ta = (int)((65.0f - sqrtf((float)(4225 - 8 * p))) * 0.5f);
    if (cum(ta + 1) <= p) ta++;
    if (cum(ta) > p) ta--;
    const int tb = ta + (p - cum(ta));
    const bool diag = (ta == tb);

    float* msh = ms + h * (TS * OC);

    // stage tile_a of this half: 16 rows x 500 floats = 2000 float4
    {
        const float4* src = reinterpret_cast<const float4*>(g_M + (size_t)ta * TS * OC);
        float4* dst = reinterpret_cast<float4*>(msh);
#pragma unroll
        for (int q = 0; q < 5; q++) dst[tl + q * 400] = src[tl + q * 400];
    }

    // load j-side rows into registers
    float a[4][5];
    float accJ[4];
#pragma unroll
    for (int r = 0; r < 4; r++) {
        const int j = tb * TS + jl + 4 * r;       // < 512 always
        const float* m = g_M + (size_t)j * OC + o * KD;
        a[r][0] = m[0]; a[r][1] = m[1]; a[r][2] = m[2];
        a[r][3] = m[3]; a[r][4] = m[4];
        accJ[r] = 0.f;
    }
    __syncthreads();

#pragma unroll
    for (int ii = 0; ii < TS; ii++) {
        const float* m = msh + ii * OC + o * KD;  // stride-5: conflict-free
        float d0 = m[0], d1 = m[1], d2 = m[2], d3 = m[3], d4 = m[4];
        float loc = 0.f;
#pragma unroll
        for (int r = 0; r < 4; r++) {
            float pa = -fabsf(d0 - a[r][0]) - fabsf(d1 - a[r][1]);
            float qa = -fabsf(d2 - a[r][2]) - fabsf(d3 - a[r][3]);
            float n = (pa + qa) - fabsf(d4 - a[r][4]);
            float e = ex2(n);
            accJ[r] += e;
            loc += e;
        }
        if (!diag) {
            // sum e over the 16 j's: reduce across the 4 jl-lanes
            loc += __shfl_xor_sync(0xffffffffu, loc, 1);
            loc += __shfl_xor_sync(0xffffffffu, loc, 2);
            if (jl == 0)
                atomicAdd(&out[(ta * TS + ii) * OUT_F + o], loc);
        }
    }

#pragma unroll
    for (int r = 0; r < 4; r++) {
        float v = accJ[r] - (diag ? 1.0f : 0.0f);
        atomicAdd(&out[(tb * TS + jl + 4 * r) * OUT_F + o], v);
    }
}

extern "C" void kernel_launch(void* const* d_in, const int* in_sizes, int n_in,
                              void* d_out, int out_size) {
    const float* x = (const float*)d_in[0];   // [512, 512]
    const float* T = (const float*)d_in[1];   // [512, 100, 5] -> [512, 500]
    float* out = (float*)d_out;               // [512, 100]

    gemm_kernel<<<dim3(64, 4), 512>>>(x, T, out);
    md_kernel<<<MD_BLOCKS, 800>>>(out);
}

// round 9
// speedup vs baseline: 1.3080x; 1.3080x over previous
#include <cuda_runtime.h>
#include <cstdint>

#define B_SZ 512
#define IN_F 512
#define OUT_F 100
#define KD 5
#define KP 6                // padded kernel dim (row stride per o)
#define OCP 600             // OUT_F * KP, padded row stride
#define LOG2E 1.4426950408889634f
#define NT 32               // number of batch tiles
#define TS 16               // tile size (NT*TS = B_SZ)
#define NP 528              // NT*(NT+1)/2 unordered tile pairs

// Scratch for M = (x @ T) * log2(e), padded layout [b][o*6+k], 1.2MB
__device__ float g_M[B_SZ * OCP];

__device__ __forceinline__ float ex2(float x) {
    float r;
    asm("ex2.approx.f32 %0, %1;" : "=f"(r) : "f"(x));
    return r;
}

// ---------------------------------------------------------------------------
// Kernel 1: M[b][o*6+k] = sum_i x[b][i] * T[i][o*5+k], scaled by log2e.
// Block: 512 threads = 64 oc-pair-lanes x 8 K-slices (kh). Each thread owns
// 4 b-rows x 2 consecutive oc over a 64-long K-slice. Grid (128, 4) = 512
// blocks (3.46/SM — better wave balance than 256). Tree-reduced via smem.
// Epilogue maps oc -> padded offset (o*6+k). Also zeroes `out`.
// ---------------------------------------------------------------------------
__global__ void __launch_bounds__(512) gemm_kernel(const float* __restrict__ x,
                                                   const float* __restrict__ T,
                                                   float* __restrict__ out) {
    __shared__ __align__(16) float xs[IN_F * 4];          // [i][bb], 8KB
    __shared__ __align__(16) float red[4 * 4 * 128];      // 4 slices x 4 bb, 8KB

    const int t = threadIdx.x;
    const int lane = t & 63;               // oc-pair lane
    const int kh = t >> 6;                 // 0..7
    const int b0 = blockIdx.x * 4;
    const int oc0 = blockIdx.y * 128;
    const int oc = oc0 + lane * 2;
    const bool ocv = (oc < OUT_F * KD);

    if (blockIdx.y == 0) {
        int idx = blockIdx.x * 512 + t;
        if (idx < B_SZ * OUT_F) out[idx] = 0.0f;
    }

    // cooperative transpose load: x[b0+bb][i] -> xs[i*4+bb]
    for (int idx = t; idx < IN_F * 4; idx += 512) {
        int bb = idx >> 9;
        int i = idx & (IN_F - 1);
        xs[i * 4 + bb] = x[(b0 + bb) * IN_F + i];
    }
    __syncthreads();

    float accx[4] = {0.f, 0.f, 0.f, 0.f};
    float accy[4] = {0.f, 0.f, 0.f, 0.f};

    if (ocv) {
        const float* tp = T + (size_t)(kh * 64) * (OUT_F * KD) + oc;
        const float* xp = xs + kh * 64 * 4;
#pragma unroll 8
        for (int i = 0; i < 64; i++) {
            float2 tv = *reinterpret_cast<const float2*>(tp + i * (OUT_F * KD));
            float4 xa = *reinterpret_cast<const float4*>(xp + i * 4);
            accx[0] += xa.x * tv.x; accy[0] += xa.x * tv.y;
            accx[1] += xa.y * tv.x; accy[1] += xa.y * tv.y;
            accx[2] += xa.z * tv.x; accy[2] += xa.z * tv.y;
            accx[3] += xa.w * tv.x; accy[3] += xa.w * tv.y;
        }
    }

    // tree reduction of 8 kh-slices (3 steps)
    if (kh >= 4) {
        float* rp = red + (kh - 4) * 512 + lane * 2;
#pragma unroll
        for (int bb = 0; bb < 4; bb++) { rp[bb * 128] = accx[bb]; rp[bb * 128 + 1] = accy[bb]; }
    }
    __syncthreads();
    if (kh < 4) {
        const float* rp = red + kh * 512 + lane * 2;
#pragma unroll
        for (int bb = 0; bb < 4; bb++) { accx[bb] += rp[bb * 128]; accy[bb] += rp[bb * 128 + 1]; }
    }
    __syncthreads();
    if (kh == 2 || kh == 3) {
        float* rp = red + (kh - 2) * 512 + lane * 2;
#pragma unroll
        for (int bb = 0; bb < 4; bb++) { rp[bb * 128] = accx[bb]; rp[bb * 128 + 1] = accy[bb]; }
    }
    __syncthreads();
    if (kh < 2) {
        const float* rp = red + kh * 512 + lane * 2;
#pragma unroll
        for (int bb = 0; bb < 4; bb++) { accx[bb] += rp[bb * 128]; accy[bb] += rp[bb * 128 + 1]; }
    }
    __syncthreads();
    if (kh == 1) {
        float* rp = red + lane * 2;
#pragma unroll
        for (int bb = 0; bb < 4; bb++) { rp[bb * 128] = accx[bb]; rp[bb * 128 + 1] = accy[bb]; }
    }
    __syncthreads();
    if (kh == 0 && ocv) {
        // padded offsets for oc and oc+1
        const int o0 = oc / 5, k0 = oc - o0 * 5;
        const int oc1 = oc + 1;
        const int o1 = oc1 / 5, k1 = oc1 - o1 * 5;
#pragma unroll
        for (int bb = 0; bb < 4; bb++) {
            float sx = (accx[bb] + red[bb * 128 + lane * 2 + 0]) * LOG2E;
            float sy = (accy[bb] + red[bb * 128 + lane * 2 + 1]) * LOG2E;
            g_M[(size_t)(b0 + bb) * OCP + o0 * KP + k0] = sx;
            g_M[(size_t)(b0 + bb) * OCP + o1 * KP + k1] = sy;
        }
    }
}

// ---------------------------------------------------------------------------
// Kernel 2 (symmetric, padded vector loads): one block per unordered tile
// pair (ta <= tb), 32 tiles of 16 rows -> 528 blocks. Block 416 threads;
// t<400: o = t>>2, jl = t&3, 4 j-rows per thread (JR=4). Padded KP=6 rows:
// d-loads are 2x LDS.64 + 1x LDS.32 (conflict-free: banks 6o mod 32 distinct
// over the 8 o's per warp). occ-3 (39 warps/SM), smem tile 38.4KB.
// ---------------------------------------------------------------------------
__global__ void __launch_bounds__(416, 3) md_kernel(float* __restrict__ out) {
    __shared__ __align__(16) float ms[TS * OCP];  // 38.4KB

    // decode blockIdx.x -> (ta, tb), upper triangle row-major
    int rem = blockIdx.x;
    int ta = 0;
    while (rem >= NT - ta) { rem -= NT - ta; ta++; }
    const int tb = ta + rem;
    const bool diag = (ta == tb);

    const int t = threadIdx.x;
    const bool act = (t < 400);
    const int o = act ? (t >> 2) : 99;   // clamp for safe reads
    const int jl = t & 3;

    // stage tile_a: 16 rows x 600 floats = 2400 float4
    {
        const float4* src = reinterpret_cast<const float4*>(g_M + (size_t)ta * TS * OCP);
        float4* dst = reinterpret_cast<float4*>(ms);
        for (int i = t; i < 2400; i += 416) dst[i] = src[i];
    }

    // load j-side rows into registers (vector LDG from padded rows)
    float a[4][5];
    float accJ[4];
#pragma unroll
    for (int r = 0; r < 4; r++) {
        const int j = tb * TS + jl + 4 * r;       // < 512 always
        const float* m = g_M + (size_t)j * OCP + o * KP;
        float2 v01 = *reinterpret_cast<const float2*>(m);
        float2 v23 = *reinterpret_cast<const float2*>(m + 2);
        a[r][0] = v01.x; a[r][1] = v01.y;
        a[r][2] = v23.x; a[r][3] = v23.y;
        a[r][4] = m[4];
        accJ[r] = 0.f;
    }
    __syncthreads();

    const float* mp = ms + o * KP;

#pragma unroll
    for (int ii = 0; ii < TS; ii++) {
        const float* m = mp + ii * OCP;
        float2 d01 = *reinterpret_cast<const float2*>(m);
        float2 d23 = *reinterpret_cast<const float2*>(m + 2);
        float d4 = m[4];
        float loc = 0.f;
#pragma unroll
        for (int r = 0; r < 4; r++) {
            float pa = -fabsf(d01.x - a[r][0]) - fabsf(d01.y - a[r][1]);
            float qa = -fabsf(d23.x - a[r][2]) - fabsf(d23.y - a[r][3]);
            float n = (pa + qa) - fabsf(d4 - a[r][4]);
            float e = ex2(n);
            accJ[r] += e;
            loc += e;
        }
        if (!diag) {
            // sum e over the 16 j's: reduce across the 4 jl-lanes
            loc += __shfl_xor_sync(0xffffffffu, loc, 1);
            loc += __shfl_xor_sync(0xffffffffu, loc, 2);
            if (act && jl == 0)
                atomicAdd(&out[(ta * TS + ii) * OUT_F + o], loc);
        }
    }

    if (act) {
#pragma unroll
        for (int r = 0; r < 4; r++) {
            float v = accJ[r] - (diag ? 1.0f : 0.0f);
            atomicAdd(&out[(tb * TS + jl + 4 * r) * OUT_F + o], v);
        }
    }
}

extern "C" void kernel_launch(void* const* d_in, const int* in_sizes, int n_in,
                              void* d_out, int out_size) {
    const float* x = (const float*)d_in[0];   // [512, 512]
    const float* T = (const float*)d_in[1];   // [512, 100, 5] -> [512, 500]
    float* out = (float*)d_out;               // [512, 100]

    gemm_kernel<<<dim3(128, 4), 512>>>(x, T, out);
    md_kernel<<<NP, 416>>>(out);
}